// round 13
// baseline (speedup 1.0000x reference)
#include <cuda_runtime.h>
#include <math.h>

#define BB   2048
#define TT_  16
#define DD   2048
#define DHH  1024
#define NCLS 174
#define DT   32768      // D*T per sample
#define NN   32768      // GEMM N = B*T
#define NU   512

// ---------------- scratch (static device allocations; no cudaMalloc) ----------------
__device__ float g_h[(size_t)BB * DT];          // 256 MB  current hidden state, flat [B][D*T]
__device__ float g_c1[(size_t)3072 * NN];       // 384 MB  theta/phi/g stacked  [3072][B*T]
__device__ float g_ctxin[(size_t)DHH * NN];     // 128 MB  context, GEMM2 B operand [1024][B*T]
__device__ float g_fc1[(size_t)BB * NU];        // 4 MB    fc1 raw accumulators
__device__ float g_inv[DD], g_cc[DD], g_cA[DD], g_cB[DD], g_cC[DD];

// ---------------- BN coefficient prep ----------------
__global__ void prep_kernel(const float* __restrict__ gamma, const float* __restrict__ beta,
                            const float* __restrict__ mean,  const float* __restrict__ var)
{
    int d = blockIdx.x * 256 + threadIdx.x;
    if (d < DD) {
        float inv = gamma[d] / sqrtf(var[d] + 1e-5f);
        float c   = beta[d] - mean[d] * inv;
        g_inv[d] = inv;
        g_cc[d]  = c;
        g_cA[d]  = 1.f + inv * inv;          // h coefficient
        g_cB[d]  = inv * inv;                // ctx coefficient
        g_cC[d]  = c * (2.f * inv + 1.f);    // constant
    }
}

// ---------------- templated 128x128 SGEMM ----------------
// MODE 0: C1 = [theta;phi;g] @ Z,  Z[k][n] = h*inv[k]+c[k] gathered from g_h (fused)
// MODE 1: h-update epilogue: h = h*cA + (W @ ctxin)*cB + cC  (in place on g_h)
// MODE 2: fc1 split-K: A[m][k] = relu(h*inv+c+x), B[k][n] = fc1_w[n][k], atomicAdd to g_fc1
template<int MODE>
__global__ void __launch_bounds__(256, 2) sgemm_kernel(
    const float* __restrict__ PA0, const float* __restrict__ PA1,
    const float* __restrict__ PA2, const float* __restrict__ PB,
    const float* __restrict__ PX, int K, int lda)
{
    __shared__ __align__(16) float As[2][16][132];
    __shared__ __align__(16) float Bs[2][16][132];

    const int tid = threadIdx.x;
    const int tx = tid & 15, ty = tid >> 4;
    const int m0 = blockIdx.x * 128;
    const int n0 = blockIdx.y * 128;
    const int kbase = (MODE == 2) ? (int)blockIdx.z * K : 0;

    const float* Aptr = PA0;
    if (MODE == 0) {
        int sel = m0 >> 10;
        const float* base = (sel == 0) ? PA0 : (sel == 1) ? PA1 : PA2;
        Aptr = base + (size_t)(m0 & 1023) * lda;
    } else if (MODE == 1) {
        Aptr = PA0 + (size_t)m0 * lda;
    }

    float4 sAa[2], sAx[2], sBb[2];

    auto gload = [&](int kt) {
        #pragma unroll
        for (int it = 0; it < 2; it++) {
            int idx = tid + it * 256;
            {   // A tile: 128 rows x 16 k
                int r = idx >> 2, q = idx & 3;
                int gk = kbase + kt * 16 + q * 4;
                if (MODE == 2) {
                    size_t off = (size_t)(m0 + r) * DT + gk;
                    sAa[it] = *(const float4*)(g_h + off);
                    sAx[it] = *(const float4*)(PX + off);
                } else {
                    sAa[it] = *(const float4*)(Aptr + (size_t)r * lda + gk);
                }
            }
            {   // B tile: 16 k x 128 n
                if (MODE == 0) {
                    int k = idx >> 5, q = idx & 31;
                    size_t addr = (size_t)((n0 >> 4) + (q >> 2)) * DT
                                + (size_t)(kt * 16 + k) * 16 + (q & 3) * 4;
                    sBb[it] = *(const float4*)(g_h + addr);
                } else if (MODE == 1) {
                    int k = idx >> 5, q = idx & 31;
                    sBb[it] = *(const float4*)(g_ctxin + (size_t)(kt * 16 + k) * NN + n0 + q * 4);
                } else {
                    int n = idx >> 2, q = idx & 3;
                    sBb[it] = *(const float4*)(PB + (size_t)(n0 + n) * DT + kbase + kt * 16 + q * 4);
                }
            }
        }
    };

    auto sstore = [&](int buf, int kt) {
        #pragma unroll
        for (int it = 0; it < 2; it++) {
            int idx = tid + it * 256;
            {   // A (transposed store)
                int r = idx >> 2, q = idx & 3;
                float4 a = sAa[it];
                if (MODE == 2) {
                    int kd = (kbase + kt * 16) >> 4;   // constant within 16-wide k-tile
                    float iv = g_inv[kd], cc = g_cc[kd];
                    float4 x4 = sAx[it];
                    a.x = fmaxf(fmaf(a.x, iv, cc) + x4.x, 0.f);
                    a.y = fmaxf(fmaf(a.y, iv, cc) + x4.y, 0.f);
                    a.z = fmaxf(fmaf(a.z, iv, cc) + x4.z, 0.f);
                    a.w = fmaxf(fmaf(a.w, iv, cc) + x4.w, 0.f);
                }
                As[buf][q * 4 + 0][r] = a.x;
                As[buf][q * 4 + 1][r] = a.y;
                As[buf][q * 4 + 2][r] = a.z;
                As[buf][q * 4 + 3][r] = a.w;
            }
            {   // B
                if (MODE == 2) {
                    int n = idx >> 2, q = idx & 3;
                    float4 v = sBb[it];
                    Bs[buf][q * 4 + 0][n] = v.x;
                    Bs[buf][q * 4 + 1][n] = v.y;
                    Bs[buf][q * 4 + 2][n] = v.z;
                    Bs[buf][q * 4 + 3][n] = v.w;
                } else {
                    int k = idx >> 5, q = idx & 31;
                    float4 v = sBb[it];
                    if (MODE == 0) {
                        int gk = kt * 16 + k;
                        float iv = g_inv[gk], cc = g_cc[gk];
                        v.x = fmaf(v.x, iv, cc);
                        v.y = fmaf(v.y, iv, cc);
                        v.z = fmaf(v.z, iv, cc);
                        v.w = fmaf(v.w, iv, cc);
                    }
                    *(float4*)&Bs[buf][k][q * 4] = v;
                }
            }
        }
    };

    float acc[8][8];
    #pragma unroll
    for (int i = 0; i < 8; i++)
        #pragma unroll
        for (int j = 0; j < 8; j++) acc[i][j] = 0.f;

    const int ntiles = K / 16;
    gload(0);
    sstore(0, 0);
    __syncthreads();

    for (int kt = 0; kt < ntiles; kt++) {
        if (kt + 1 < ntiles) gload(kt + 1);
        const int cur = kt & 1;
        #pragma unroll
        for (int kk = 0; kk < 16; kk++) {
            float4 a0 = *(const float4*)&As[cur][kk][ty * 4];
            float4 a1 = *(const float4*)&As[cur][kk][64 + ty * 4];
            float4 b0 = *(const float4*)&Bs[cur][kk][tx * 4];
            float4 b1 = *(const float4*)&Bs[cur][kk][64 + tx * 4];
            float av[8] = {a0.x, a0.y, a0.z, a0.w, a1.x, a1.y, a1.z, a1.w};
            float bv[8] = {b0.x, b0.y, b0.z, b0.w, b1.x, b1.y, b1.z, b1.w};
            #pragma unroll
            for (int i = 0; i < 8; i++)
                #pragma unroll
                for (int j = 0; j < 8; j++)
                    acc[i][j] = fmaf(av[i], bv[j], acc[i][j]);
        }
        if (kt + 1 < ntiles) sstore(cur ^ 1, kt + 1);
        __syncthreads();
    }

    // ---- epilogue ----
    #pragma unroll
    for (int i = 0; i < 8; i++) {
        int row = m0 + ((i < 4) ? (ty * 4 + i) : (64 + ty * 4 + i - 4));
        if (MODE == 0) {
            *(float4*)&g_c1[(size_t)row * NN + n0 + tx * 4] =
                make_float4(acc[i][0], acc[i][1], acc[i][2], acc[i][3]);
            *(float4*)&g_c1[(size_t)row * NN + n0 + 64 + tx * 4] =
                make_float4(acc[i][4], acc[i][5], acc[i][6], acc[i][7]);
        } else if (MODE == 1) {
            float ca = g_cA[row], cb = g_cB[row], c3 = g_cC[row];
            #pragma unroll
            for (int half = 0; half < 2; half++) {
                int n = n0 + half * 64 + tx * 4;
                size_t p = (size_t)(n >> 4) * DT + (size_t)row * 16 + (n & 15);
                float4 h4 = *(float4*)&g_h[p];
                h4.x = h4.x * ca + acc[i][half * 4 + 0] * cb + c3;
                h4.y = h4.y * ca + acc[i][half * 4 + 1] * cb + c3;
                h4.z = h4.z * ca + acc[i][half * 4 + 2] * cb + c3;
                h4.w = h4.w * ca + acc[i][half * 4 + 3] * cb + c3;
                *(float4*)&g_h[p] = h4;
            }
        } else {
            #pragma unroll
            for (int half = 0; half < 2; half++) {
                int n = n0 + half * 64 + tx * 4;
                float* dst = &g_fc1[(size_t)row * NU + n];
                atomicAdd(dst + 0, acc[i][half * 4 + 0]);
                atomicAdd(dst + 1, acc[i][half * 4 + 1]);
                atomicAdd(dst + 2, acc[i][half * 4 + 2]);
                atomicAdd(dst + 3, acc[i][half * 4 + 3]);
            }
        }
    }
}

// ---------------- per-sample 16x16 attention ----------------
// thread (t,s) accumulates scores; then softmax; then context -> g_ctxin
__global__ void __launch_bounds__(256) attention_kernel()
{
    __shared__ __align__(16) float th[128][16];
    __shared__ __align__(16) float ph[128][16];
    __shared__ float Ssm[16][17];
    __shared__ float Asm[16][17];

    const int tid = threadIdx.x;
    const int b = blockIdx.x;
    const int tt = tid >> 4, ss = tid & 15;
    const size_t cb = (size_t)b * 16;

    float sacc = 0.f;
    for (int oc = 0; oc < 1024; oc += 128) {
        #pragma unroll
        for (int i = 0; i < 2; i++) {
            int idx = tid + i * 256;
            int o = idx >> 2, q = idx & 3;
            *(float4*)&th[o][q * 4] = *(const float4*)&g_c1[(size_t)(oc + o) * NN + cb + q * 4];
            *(float4*)&ph[o][q * 4] = *(const float4*)&g_c1[(size_t)(1024 + oc + o) * NN + cb + q * 4];
        }
        __syncthreads();
        #pragma unroll 8
        for (int o = 0; o < 128; o++)
            sacc = fmaf(th[o][tt], ph[o][ss], sacc);
        __syncthreads();
    }
    Ssm[tt][ss] = sacc * (1.0f / 1024.0f);
    __syncthreads();

    float m = Ssm[tt][0];
    #pragma unroll
    for (int j = 1; j < 16; j++) m = fmaxf(m, Ssm[tt][j]);
    float e = expf(Ssm[tt][ss] - m);
    Asm[tt][ss] = e;
    __syncthreads();
    float sum = 0.f;
    #pragma unroll
    for (int j = 0; j < 16; j++) sum += Asm[tt][j];
    float alpha = e / sum;
    __syncthreads();
    Asm[tt][ss] = alpha;
    __syncthreads();

    // context: ctxin[o][b*16+t] = sum_s Asm[t][s] * g[o][s]
    #pragma unroll
    for (int oo = 0; oo < 4; oo++) {
        int o = tid + oo * 256;
        const float* gr = &g_c1[(size_t)(2048 + o) * NN + cb];
        float4 g0 = *(const float4*)(gr);
        float4 g1 = *(const float4*)(gr + 4);
        float4 g2 = *(const float4*)(gr + 8);
        float4 g3 = *(const float4*)(gr + 12);
        float gv[16] = {g0.x, g0.y, g0.z, g0.w, g1.x, g1.y, g1.z, g1.w,
                        g2.x, g2.y, g2.z, g2.w, g3.x, g3.y, g3.z, g3.w};
        float ct[16];
        #pragma unroll
        for (int t = 0; t < 16; t++) {
            float s2 = 0.f;
            #pragma unroll
            for (int s = 0; s < 16; s++) s2 = fmaf(Asm[t][s], gv[s], s2);
            ct[t] = s2;
        }
        float* dst = &g_ctxin[(size_t)o * NN + cb];
        *(float4*)(dst)      = make_float4(ct[0],  ct[1],  ct[2],  ct[3]);
        *(float4*)(dst + 4)  = make_float4(ct[4],  ct[5],  ct[6],  ct[7]);
        *(float4*)(dst + 8)  = make_float4(ct[8],  ct[9],  ct[10], ct[11]);
        *(float4*)(dst + 12) = make_float4(ct[12], ct[13], ct[14], ct[15]);
    }
}

// ---------------- fc2 ----------------
__global__ void __launch_bounds__(192) fc2_kernel(const float* __restrict__ fc1b,
                                                  const float* __restrict__ fc2w,
                                                  const float* __restrict__ fc2b,
                                                  float* __restrict__ out)
{
    __shared__ float s[NU];
    int b = blockIdx.x;
    for (int u = threadIdx.x; u < NU; u += 192)
        s[u] = fmaxf(g_fc1[(size_t)b * NU + u] + fc1b[u], 0.f);
    __syncthreads();
    int cls = threadIdx.x;
    if (cls < NCLS) {
        const float* w = fc2w + (size_t)cls * NU;
        float a = 0.f;
        #pragma unroll 8
        for (int u = 0; u < NU; u++) a = fmaf(s[u], w[u], a);
        out[(size_t)b * NCLS + cls] = a + fc2b[cls];
    }
}

// ---------------- host ----------------
extern "C" void kernel_launch(void* const* d_in, const int* in_sizes, int n_in,
                              void* d_out, int out_size)
{
    (void)in_sizes; (void)n_in; (void)out_size;
    const float* x     = (const float*)d_in[0];
    const float* thw   = (const float*)d_in[1];
    const float* phw   = (const float*)d_in[2];
    const float* gw    = (const float*)d_in[3];
    const float* Ww    = (const float*)d_in[4];
    const float* gamma = (const float*)d_in[5];
    const float* beta  = (const float*)d_in[6];
    const float* mean  = (const float*)d_in[7];
    const float* var   = (const float*)d_in[8];
    const float* fc1w  = (const float*)d_in[9];
    const float* fc1b  = (const float*)d_in[10];
    const float* fc2w  = (const float*)d_in[11];
    const float* fc2b  = (const float*)d_in[12];
    float* out = (float*)d_out;

    void* hsym = nullptr; cudaGetSymbolAddress(&hsym, g_h);
    void* fsym = nullptr; cudaGetSymbolAddress(&fsym, g_fc1);

    cudaMemcpyAsync(hsym, x, sizeof(float) * (size_t)BB * DT, cudaMemcpyDeviceToDevice, 0);
    prep_kernel<<<8, 256>>>(gamma, beta, mean, var);

    dim3 blk(256);
    dim3 grd1(24, 256);     // GEMM1: M=3072, N=32768  (m-fastest for L2 reuse of B)
    dim3 grd2(16, 256);     // GEMM2: M=2048, N=32768
    for (int it = 0; it < 16; it++) {
        sgemm_kernel<0><<<grd1, blk>>>(thw, phw, gw, nullptr, nullptr, 2048, 2048);
        attention_kernel<<<BB, 256>>>();
        sgemm_kernel<1><<<grd2, blk>>>(Ww, nullptr, nullptr, nullptr, nullptr, 1024, 1024);
    }

    cudaMemsetAsync(fsym, 0, sizeof(float) * (size_t)BB * NU, 0);
    dim3 grdf(16, 4, 4);    // fc1: M=2048 (b), N=512 (u), split-K = 4 x 8192
    sgemm_kernel<2><<<grdf, blk>>>(nullptr, nullptr, nullptr, fc1w, x, 8192, 0);
    fc2_kernel<<<BB, 192>>>(fc1b, fc2w, fc2b, out);
}